// round 1
// baseline (speedup 1.0000x reference)
#include <cuda_runtime.h>
#include <cstddef>

#define P_C     16
#define K_C     256
#define W_C     8
#define F_IN_C  128
#define F_OUT_C 128
#define N_SRC_MAX 200000
#define N_DST_MAX 100000

// Scratch (allocation-free rule: __device__ globals)
__device__ float g_feat[(size_t)N_SRC_MAX * F_IN_C];     // decoded per-source features
__device__ float g_hneigh[(size_t)N_DST_MAX * F_IN_C];   // mean-aggregated neighbor features

// ---------------------------------------------------------------------------
// Kernel 1: decode feat[s, p*8+w] = codebook[p, codes[s,p], w]
// 32 threads per source, each lane writes one float4 (4 features).
// ---------------------------------------------------------------------------
__global__ void decode_kernel(const int* __restrict__ codes,
                              const float* __restrict__ codebook,
                              int n_src) {
    int gid = blockIdx.x * blockDim.x + threadIdx.x;
    int s = gid >> 5;
    if (s >= n_src) return;
    int l = gid & 31;
    int p  = l >> 1;            // feature f = l*4.. -> p = f/8 = l/2
    int w4 = (l & 1) << 2;      // w base = (f%8) chunk
    int code = __ldg(codes + s * P_C + p);
    float4 v = *reinterpret_cast<const float4*>(
        codebook + ((size_t)((p << 8) + code)) * W_C + w4);
    *reinterpret_cast<float4*>(g_feat + (size_t)s * F_IN_C + (l << 2)) = v;
}

// ---------------------------------------------------------------------------
// Kernel 2: gather + mean. One warp per destination.
// Lane l accumulates features [4l, 4l+4). Indices preloaded + shfl-broadcast.
// ---------------------------------------------------------------------------
__global__ void gather_kernel(const int* __restrict__ indices,
                              const int* __restrict__ indptr,
                              int n_dst) {
    int warp = (blockIdx.x * blockDim.x + threadIdx.x) >> 5;
    int lane = threadIdx.x & 31;
    if (warp >= n_dst) return;

    int start = __ldg(indptr + warp);
    int end   = __ldg(indptr + warp + 1);
    int deg   = end - start;

    float4 acc = make_float4(0.f, 0.f, 0.f, 0.f);
    int my_idx = (lane < deg) ? __ldg(indices + start + lane) : 0;

    if (deg == 16) {
#pragma unroll
        for (int e = 0; e < 16; e++) {
            int src = __shfl_sync(0xffffffffu, my_idx, e);
            float4 v = *reinterpret_cast<const float4*>(
                g_feat + (size_t)src * F_IN_C + (lane << 2));
            acc.x += v.x; acc.y += v.y; acc.z += v.z; acc.w += v.w;
        }
    } else {
        for (int e = 0; e < deg; e++) {
            int src = (e < 32) ? __shfl_sync(0xffffffffu, my_idx, e)
                               : __ldg(indices + start + e);
            float4 v = *reinterpret_cast<const float4*>(
                g_feat + (size_t)src * F_IN_C + (lane << 2));
            acc.x += v.x; acc.y += v.y; acc.z += v.z; acc.w += v.w;
        }
    }
    float s = 1.0f / fmaxf((float)deg, 1.0f);
    acc.x *= s; acc.y *= s; acc.z *= s; acc.w *= s;
    *reinterpret_cast<float4*>(g_hneigh + (size_t)warp * F_IN_C + (lane << 2)) = acc;
}

// ---------------------------------------------------------------------------
// Kernel 3: out = h_neigh @ Wn.T + h_self @ Ws.T + b
// Treated as M x 128 GEMM with K=256 (concatenated). 128x128 CTA tile,
// 8x8 register tile per thread (256 threads), k-major smem, double buffered.
// ---------------------------------------------------------------------------
#define MT 128
#define KT 16

__device__ __forceinline__ void load_A_tile(float dst[KT][MT],
                                            const float* __restrict__ src,
                                            int m0, int kk, int tid, int n_dst) {
#pragma unroll
    for (int i = 0; i < 2; i++) {
        int f4  = tid + (i << 8);
        int row = f4 >> 2;
        int c   = f4 & 3;
        int gr  = m0 + row;
        if (gr > n_dst - 1) gr = n_dst - 1;
        float4 v = *reinterpret_cast<const float4*>(
            src + (size_t)gr * F_IN_C + kk + (c << 2));
        dst[(c << 2) + 0][row] = v.x;
        dst[(c << 2) + 1][row] = v.y;
        dst[(c << 2) + 2][row] = v.z;
        dst[(c << 2) + 3][row] = v.w;
    }
}

__device__ __forceinline__ void load_B_tile(float dst[KT][128],
                                            const float* __restrict__ src,
                                            int kk, int tid) {
#pragma unroll
    for (int i = 0; i < 2; i++) {
        int f4  = tid + (i << 8);
        int row = f4 >> 2;
        int c   = f4 & 3;
        float4 v = *reinterpret_cast<const float4*>(
            src + (size_t)row * F_IN_C + kk + (c << 2));
        dst[(c << 2) + 0][row] = v.x;
        dst[(c << 2) + 1][row] = v.y;
        dst[(c << 2) + 2][row] = v.z;
        dst[(c << 2) + 3][row] = v.w;
    }
}

__global__ __launch_bounds__(256, 2) void gemm_kernel(
    const float* __restrict__ hself,
    const float* __restrict__ Wn,
    const float* __restrict__ Ws,
    const float* __restrict__ bias,
    float* __restrict__ out,
    int n_dst) {
    __shared__ float As[2][KT][MT];
    __shared__ float Bs[2][KT][128];

    int tid = threadIdx.x;
    int tx  = tid & 15;   // n-group (8 cols)
    int ty  = tid >> 4;   // m-group (8 rows)
    int m0  = blockIdx.x * MT;

    float acc[8][8];
#pragma unroll
    for (int i = 0; i < 8; i++)
#pragma unroll
        for (int j = 0; j < 8; j++) acc[i][j] = 0.f;

    // prologue: tile 0 (k in [0,16) -> neighbor half)
    load_A_tile(As[0], g_hneigh, m0, 0, tid, n_dst);
    load_B_tile(Bs[0], Wn, 0, tid);
    __syncthreads();

    const int NTILES = 256 / KT;  // 16
    for (int t = 0; t < NTILES; t++) {
        int cur = t & 1;
        int nxt = cur ^ 1;
        if (t + 1 < NTILES) {
            int kt = (t + 1) * KT;
            const float* Asrc = (kt < 128) ? (const float*)g_hneigh : hself;
            const float* Bsrc = (kt < 128) ? Wn : Ws;
            int kk = kt & 127;
            load_A_tile(As[nxt], Asrc, m0, kk, tid, n_dst);
            load_B_tile(Bs[nxt], Bsrc, kk, tid);
        }
#pragma unroll
        for (int k = 0; k < KT; k++) {
            float4 a0 = *reinterpret_cast<const float4*>(&As[cur][k][ty * 8]);
            float4 a1 = *reinterpret_cast<const float4*>(&As[cur][k][ty * 8 + 4]);
            float4 b0 = *reinterpret_cast<const float4*>(&Bs[cur][k][tx * 8]);
            float4 b1 = *reinterpret_cast<const float4*>(&Bs[cur][k][tx * 8 + 4]);
            float a[8] = {a0.x, a0.y, a0.z, a0.w, a1.x, a1.y, a1.z, a1.w};
            float b[8] = {b0.x, b0.y, b0.z, b0.w, b1.x, b1.y, b1.z, b1.w};
#pragma unroll
            for (int i = 0; i < 8; i++)
#pragma unroll
                for (int j = 0; j < 8; j++)
                    acc[i][j] += a[i] * b[j];
        }
        __syncthreads();
    }

    // epilogue: + bias, store
    float bj[8];
#pragma unroll
    for (int j = 0; j < 8; j++) bj[j] = __ldg(bias + tx * 8 + j);

#pragma unroll
    for (int i = 0; i < 8; i++) {
        int gr = m0 + ty * 8 + i;
        if (gr < n_dst) {
            float4 o0 = make_float4(acc[i][0] + bj[0], acc[i][1] + bj[1],
                                    acc[i][2] + bj[2], acc[i][3] + bj[3]);
            float4 o1 = make_float4(acc[i][4] + bj[4], acc[i][5] + bj[5],
                                    acc[i][6] + bj[6], acc[i][7] + bj[7]);
            *reinterpret_cast<float4*>(out + (size_t)gr * F_OUT_C + tx * 8)     = o0;
            *reinterpret_cast<float4*>(out + (size_t)gr * F_OUT_C + tx * 8 + 4) = o1;
        }
    }
}

// ---------------------------------------------------------------------------
// Launch
// ---------------------------------------------------------------------------
extern "C" void kernel_launch(void* const* d_in, const int* in_sizes, int n_in,
                              void* d_out, int out_size) {
    const int*   codes    = (const int*)d_in[0];
    const int*   indices  = (const int*)d_in[1];
    const int*   indptr   = (const int*)d_in[2];
    const float* h_self   = (const float*)d_in[3];
    const float* codebook = (const float*)d_in[4];
    const float* Wn       = (const float*)d_in[5];
    const float* Ws       = (const float*)d_in[6];
    const float* b_self   = (const float*)d_in[7];
    float* out = (float*)d_out;

    int n_src = in_sizes[0] / P_C;
    int n_dst = in_sizes[2] - 1;

    // K1: decode (32 threads per source)
    {
        int total = n_src * 32;
        decode_kernel<<<(total + 255) / 256, 256>>>(codes, codebook, n_src);
    }
    // K2: gather+mean (one warp per dst)
    {
        int total = n_dst * 32;
        gather_kernel<<<(total + 255) / 256, 256>>>(indices, indptr, n_dst);
    }
    // K3: fused dual GEMM + bias
    {
        int blocks = (n_dst + MT - 1) / MT;
        gemm_kernel<<<blocks, 256>>>(h_self, Wn, Ws, b_self, out, n_dst);
    }
}